// round 3
// baseline (speedup 1.0000x reference)
#include <cuda_runtime.h>
#include <cuda_bf16.h>

// Problem constants (shapes fixed by the dataset)
#define NN_MAX 100000
#define NG_MAX 1024
#define D 128

// Scratch (allocation-free rule: __device__ globals; float4 => 16B alignment)
__device__ float4 g_agg [NN_MAX * D / 4];
__device__ float4 g_h   [NN_MAX * D / 4];
__device__ float4 g_x1  [NN_MAX * D / 4];
__device__ float4 g_x2  [NN_MAX * D / 4];
__device__ float4 g_pool[NG_MAX * D / 4];

// index-width flag: 1 => int64 indices, 0 => int32 indices
__device__ int g_is64;

// ---------------- packed f32x2 helpers (Blackwell FFMA2) ----------------
__device__ __forceinline__ unsigned long long pack2(float x, float y) {
    unsigned long long r;
    asm("mov.b64 %0, {%1, %2};" : "=l"(r) : "f"(x), "f"(y));
    return r;
}
__device__ __forceinline__ unsigned long long fma2(unsigned long long a,
                                                   unsigned long long b,
                                                   unsigned long long c) {
    unsigned long long d;
    asm("fma.rn.f32x2 %0, %1, %2, %3;" : "=l"(d) : "l"(a), "l"(b), "l"(c));
    return d;
}
__device__ __forceinline__ void unpack2(unsigned long long v, float& x, float& y) {
    asm("mov.b64 {%0, %1}, %2;" : "=f"(x), "=f"(y) : "l"(v));
}

// ---------------- dtype detector ----------------
// If the buffer holds int64 values < 2^31, every odd int32 word is 0.
// With genuinely-int32 random indices in [0, 100000), 2048 consecutive odd
// words being all zero has probability ~0.
__global__ void detect_kernel(const int* __restrict__ ei32) {
    int any = 0;
    for (int i = threadIdx.x; i < 2048; i += 32)
        if (ei32[2 * i + 1] != 0) any = 1;
    any = __any_sync(0xffffffffu, any);
    if (threadIdx.x == 0) g_is64 = any ? 0 : 1;
}

// ---------------- zero kernel ----------------
__global__ void zero_kernel(float4* __restrict__ p, int n4) {
    int i = blockIdx.x * blockDim.x + threadIdx.x;
    if (i < n4) p[i] = make_float4(0.f, 0.f, 0.f, 0.f);
}

// ---------------- edge scatter: agg[dst] += x[src] ----------------
// one warp per edge; lane handles one float4 (16B); vector red (sm_90+)
__global__ void scatter_kernel(const float* __restrict__ x,
                               const void* __restrict__ ei,
                               float* __restrict__ agg, int nE) {
    int gid = blockIdx.x * blockDim.x + threadIdx.x;
    int e = gid >> 5, lane = gid & 31;
    if (e >= nE) return;
    int s, d;
    if (g_is64) {
        const long long* p = (const long long*)ei;
        s = (int)p[e]; d = (int)p[nE + e];
    } else {
        const int* p = (const int*)ei;
        s = p[e]; d = p[nE + e];
    }
    float4 v = ((const float4*)(x + (size_t)s * D))[lane];
    float* p = agg + (size_t)d * D + lane * 4;
    asm volatile("red.global.add.v4.f32 [%0], {%1,%2,%3,%4};"
                 :: "l"(p), "f"(v.x), "f"(v.y), "f"(v.z), "f"(v.w)
                 : "memory");
}

// ---------------- global pool: pool[batch[i]] += x[i] ----------------
__global__ void pool_kernel(const float* __restrict__ x,
                            const void* __restrict__ batch,
                            float* __restrict__ pool, int n) {
    int gid = blockIdx.x * blockDim.x + threadIdx.x;
    int node = gid >> 5, lane = gid & 31;
    if (node >= n) return;
    int g;
    if (g_is64) g = (int)((const long long*)batch)[node];
    else        g = ((const int*)batch)[node];
    float4 v = ((const float4*)(x + (size_t)node * D))[lane];
    float* p = pool + (size_t)g * D + lane * 4;
    asm volatile("red.global.add.v4.f32 [%0], {%1,%2,%3,%4};"
                 :: "l"(p), "f"(v.x), "f"(v.y), "f"(v.z), "f"(v.w)
                 : "memory");
}

// ---------------- big GEMM: C = epilogue((A [+A2]) @ W + b) ----------------
// MODE 0: relu(acc + b)
// MODE 1: relu(BN(acc + b))   (eval-mode BN folded into scale/shift)
// MODE 2: acc + b
// Tile: 128 rows x 128 cols per CTA, 256 threads, 8x8 outputs/thread.
// K streamed in chunks of 16 through smem; inner loop uses packed fma.rn.f32x2.
template <int MODE>
__global__ void __launch_bounds__(256, 2)
gemm_big(const float* __restrict__ A, const float* __restrict__ A2,
         const float* __restrict__ W, const float* __restrict__ bias,
         const float* __restrict__ gamma, const float* __restrict__ beta,
         const float* __restrict__ mean, const float* __restrict__ var,
         float* __restrict__ C, int M) {
    __shared__ float Ws[16 * 128];     // [k][c]
    __shared__ float As[16 * 128];     // [k][r]  (A transposed in smem)

    int tid = threadIdx.x;
    int row0 = blockIdx.x * 128;
    int ty = tid >> 4;                 // 0..15  -> rows ty*8 .. ty*8+7
    int tx = tid & 15;                 // 0..15  -> cols tx*8 .. tx*8+7

    int r_load = tid & 127;            // row within tile this thread loads
    int kq = tid >> 7;                 // 0/1: which 8-k half this thread loads
    int grow = row0 + r_load;
    bool rvalid = grow < M;
    const float4* Arow  = (const float4*)(A + (size_t)(rvalid ? grow : 0) * D);
    const float4* A2row = A2 ? (const float4*)(A2 + (size_t)(rvalid ? grow : 0) * D) : nullptr;

    unsigned long long acc2[4][8];     // rows paired: acc2[rp][c] = {row 2rp, row 2rp+1}
#pragma unroll
    for (int i = 0; i < 4; i++)
#pragma unroll
        for (int j = 0; j < 8; j++) acc2[i][j] = 0ULL;

    for (int kc = 0; kc < 8; kc++) {
        // stage loads to registers
        float4 v0 = make_float4(0.f, 0.f, 0.f, 0.f), v1 = v0;
        if (rvalid) {
            v0 = Arow[kc * 4 + kq * 2];
            v1 = Arow[kc * 4 + kq * 2 + 1];
            if (A2row) {
                float4 u0 = A2row[kc * 4 + kq * 2];
                float4 u1 = A2row[kc * 4 + kq * 2 + 1];
                v0.x += u0.x; v0.y += u0.y; v0.z += u0.z; v0.w += u0.w;
                v1.x += u1.x; v1.y += u1.y; v1.z += u1.z; v1.w += u1.w;
            }
        }
        const float4* Wg = (const float4*)(W + kc * 16 * 128);
        float4 w0 = Wg[tid];
        float4 w1 = Wg[tid + 256];

        __syncthreads();
        int kb = kq * 8;
        As[(kb + 0) * 128 + r_load] = v0.x;
        As[(kb + 1) * 128 + r_load] = v0.y;
        As[(kb + 2) * 128 + r_load] = v0.z;
        As[(kb + 3) * 128 + r_load] = v0.w;
        As[(kb + 4) * 128 + r_load] = v1.x;
        As[(kb + 5) * 128 + r_load] = v1.y;
        As[(kb + 6) * 128 + r_load] = v1.z;
        As[(kb + 7) * 128 + r_load] = v1.w;
        ((float4*)Ws)[tid]       = w0;
        ((float4*)Ws)[tid + 256] = w1;
        __syncthreads();

#pragma unroll
        for (int k = 0; k < 16; k++) {
            const unsigned long long* a2p =
                (const unsigned long long*)&As[k * 128 + ty * 8];
            unsigned long long a0 = a2p[0], a1 = a2p[1], a2 = a2p[2], a3 = a2p[3];
            float4 wv0 = *(const float4*)&Ws[k * 128 + tx * 8];
            float4 wv1 = *(const float4*)&Ws[k * 128 + tx * 8 + 4];
            unsigned long long w2[8];
            w2[0] = pack2(wv0.x, wv0.x); w2[1] = pack2(wv0.y, wv0.y);
            w2[2] = pack2(wv0.z, wv0.z); w2[3] = pack2(wv0.w, wv0.w);
            w2[4] = pack2(wv1.x, wv1.x); w2[5] = pack2(wv1.y, wv1.y);
            w2[6] = pack2(wv1.z, wv1.z); w2[7] = pack2(wv1.w, wv1.w);
#pragma unroll
            for (int c = 0; c < 8; c++) {
                acc2[0][c] = fma2(a0, w2[c], acc2[0][c]);
                acc2[1][c] = fma2(a1, w2[c], acc2[1][c]);
                acc2[2][c] = fma2(a2, w2[c], acc2[2][c]);
                acc2[3][c] = fma2(a3, w2[c], acc2[3][c]);
            }
        }
    }

    // epilogue constants per column
    int cbase = tx * 8;
    float S[8], T[8];
#pragma unroll
    for (int ci = 0; ci < 8; ci++) {
        int c = cbase + ci;
        float b = bias[c];
        if (MODE == 1) {
            float s = gamma[c] * rsqrtf(var[c] + 1e-5f);
            S[ci] = s;
            T[ci] = beta[c] + (b - mean[c]) * s;
        } else {
            S[ci] = 1.f;
            T[ci] = b;
        }
    }

#pragma unroll
    for (int rp = 0; rp < 4; rp++) {
        float o0[8], o1[8];
#pragma unroll
        for (int ci = 0; ci < 8; ci++) {
            float lo, hi;
            unpack2(acc2[rp][ci], lo, hi);
            float a = lo * S[ci] + T[ci];
            float b = hi * S[ci] + T[ci];
            if (MODE != 2) { a = fmaxf(a, 0.f); b = fmaxf(b, 0.f); }
            o0[ci] = a; o1[ci] = b;
        }
        int row = row0 + ty * 8 + rp * 2;
        if (row < M) {
            float4* Cp = (float4*)(C + (size_t)row * D + cbase);
            Cp[0] = make_float4(o0[0], o0[1], o0[2], o0[3]);
            Cp[1] = make_float4(o0[4], o0[5], o0[6], o0[7]);
        }
        if (row + 1 < M) {
            float4* Cp = (float4*)(C + (size_t)(row + 1) * D + cbase);
            Cp[0] = make_float4(o1[0], o1[1], o1[2], o1[3]);
            Cp[1] = make_float4(o1[4], o1[5], o1[6], o1[7]);
        }
    }
}

// ---------------- small GEMM for the head (16 rows per CTA) ----------------
template <int MODE>  // 0: relu(acc+b), 2: acc+b
__global__ void __launch_bounds__(256)
gemm_small(const float* __restrict__ A, const float* __restrict__ W,
           const float* __restrict__ bias, float* __restrict__ C, int M) {
    __shared__ float Ws[16 * 128];     // [k][c] chunk
    __shared__ float As[16 * 128];     // [r][k] full K

    int tid = threadIdx.x;
    int row0 = blockIdx.x * 16;
    int ty = tid >> 4;                 // row 0..15
    int tx = tid & 15;                 // col group

    // load full 16x128 A tile (contiguous)
    const float4* Ag = (const float4*)(A + (size_t)row0 * D);
    ((float4*)As)[tid]       = Ag[tid];
    ((float4*)As)[tid + 256] = Ag[tid + 256];

    float acc[8];
#pragma unroll
    for (int i = 0; i < 8; i++) acc[i] = 0.f;

    for (int kc = 0; kc < 8; kc++) {
        const float4* Wg = (const float4*)(W + kc * 16 * 128);
        float4 w0 = Wg[tid];
        float4 w1 = Wg[tid + 256];
        __syncthreads();
        ((float4*)Ws)[tid]       = w0;
        ((float4*)Ws)[tid + 256] = w1;
        __syncthreads();
#pragma unroll
        for (int k = 0; k < 16; k++) {
            float a = As[ty * 128 + kc * 16 + k];
            float4 b0 = *(const float4*)&Ws[k * 128 + tx * 8];
            float4 b1 = *(const float4*)&Ws[k * 128 + tx * 8 + 4];
            acc[0] += a * b0.x; acc[1] += a * b0.y;
            acc[2] += a * b0.z; acc[3] += a * b0.w;
            acc[4] += a * b1.x; acc[5] += a * b1.y;
            acc[6] += a * b1.z; acc[7] += a * b1.w;
        }
    }

    int row = row0 + ty;
    if (row < M) {
        int cbase = tx * 8;
        float o[8];
#pragma unroll
        for (int ci = 0; ci < 8; ci++) {
            float v = acc[ci] + bias[cbase + ci];
            if (MODE != 2) v = fmaxf(v, 0.f);
            o[ci] = v;
        }
        float4* Cp = (float4*)(C + (size_t)row * D + cbase);
        Cp[0] = make_float4(o[0], o[1], o[2], o[3]);
        Cp[1] = make_float4(o[4], o[5], o[6], o[7]);
    }
}

extern "C" void kernel_launch(void* const* d_in, const int* in_sizes, int n_in,
                              void* d_out, int out_size) {
    const float* x    = (const float*)d_in[0];
    const void* ei    = d_in[1];
    const void* batch = d_in[2];
    const float* W1   = (const float*)d_in[3];
    const float* b1   = (const float*)d_in[4];
    const float* gam  = (const float*)d_in[5];
    const float* bet  = (const float*)d_in[6];
    const float* mu   = (const float*)d_in[7];
    const float* var  = (const float*)d_in[8];
    const float* W2   = (const float*)d_in[9];
    const float* b2   = (const float*)d_in[10];
    const float* hW1  = (const float*)d_in[11];
    const float* hb1  = (const float*)d_in[12];
    const float* hW2  = (const float*)d_in[13];
    const float* hb2  = (const float*)d_in[14];
    float* out = (float*)d_out;

    int nN = in_sizes[0] / D;          // 100000
    int nE = in_sizes[1] / 2;          // 1600000
    int nG = out_size / D;             // 1024

    void* p;
    cudaGetSymbolAddress(&p, g_agg);  float* agg  = (float*)p;
    cudaGetSymbolAddress(&p, g_h);    float* h    = (float*)p;
    cudaGetSymbolAddress(&p, g_x1);   float* x1   = (float*)p;
    cudaGetSymbolAddress(&p, g_x2);   float* x2   = (float*)p;
    cudaGetSymbolAddress(&p, g_pool); float* pool = (float*)p;

    int zeroBlocksN = (nN * 32 + 255) / 256;       // nN*128/4 float4s
    int scatBlocks  = (nE * 32 + 255) / 256;       // 1 warp per edge
    int gemmBlocks  = (nN + 127) / 128;
    int poolBlocks  = (nN * 32 + 255) / 256;

    detect_kernel<<<1, 32>>>((const int*)ei);

    const float* xin = x;
    float* xbuf[2] = {x1, x2};
    for (int l = 0; l < 3; l++) {
        zero_kernel<<<zeroBlocksN, 256>>>((float4*)agg, nN * 32);
        scatter_kernel<<<scatBlocks, 256>>>(xin, ei, agg, nE);
        gemm_big<1><<<gemmBlocks, 256>>>(xin, agg,
                                         W1 + l * D * D, b1 + l * D,
                                         gam + l * D, bet + l * D,
                                         mu + l * D, var + l * D,
                                         h, nN);
        float* xo = xbuf[l & 1];
        gemm_big<0><<<gemmBlocks, 256>>>(h, nullptr,
                                         W2 + l * D * D, b2 + l * D,
                                         nullptr, nullptr, nullptr, nullptr,
                                         xo, nN);
        xin = xo;
    }

    zero_kernel<<<(nG * 32 + 255) / 256, 256>>>((float4*)pool, nG * 32);
    pool_kernel<<<poolBlocks, 256>>>(xin, batch, pool, nN);

    gemm_small<0><<<(nG + 15) / 16, 256>>>(pool, hW1, hb1, h, nG);
    gemm_small<2><<<(nG + 15) / 16, 256>>>(h, hW2, hb2, out, nG);
}

// round 5
// speedup vs baseline: 1.5272x; 1.5272x over previous
#include <cuda_runtime.h>
#include <cuda_bf16.h>
#include <cstdint>

#define NN_MAX 100000
#define NG_MAX 1024
#define D 128
#define NE_MAX 1600000

// ---------------- device scratch (allocation-free rule) ----------------
__device__ float4 g_agg [NN_MAX * D / 4];
__device__ float4 g_h   [NN_MAX * D / 4];
__device__ float4 g_x1  [NN_MAX * D / 4];
__device__ float4 g_x2  [NN_MAX * D / 4];
__device__ float4 g_pool[NG_MAX * D / 4];
// CSR
__device__ int g_deg [NN_MAX + 64];
__device__ int g_off [NN_MAX + 64];
__device__ int g_cur [NN_MAX + 64];
__device__ int g_esrc[NE_MAX];
__device__ int g_part [64];
__device__ int g_part2[64];
// weight images: per matrix, [hi nh0][hi nh1][lo nh0][lo nh1], each 4608 u32 (64 kpair x 72)
__device__ uint32_t g_wtB[8][4 * 4608];
__device__ float g_st[8][2][128];     // [matrix][S/T][col]
__device__ int g_is64;

// ---------------- helpers ----------------
__device__ __forceinline__ int edge_idx(const void* ei, int i) {
    if (g_is64) return (int)((const long long*)ei)[i];
    return ((const int*)ei)[i];
}

__device__ __forceinline__ void mma16816(float* c, const uint32_t* a, const uint32_t* b) {
    asm volatile(
        "mma.sync.aligned.m16n8k16.row.col.f32.bf16.bf16.f32 "
        "{%0,%1,%2,%3}, {%4,%5,%6,%7}, {%8,%9}, {%0,%1,%2,%3};"
        : "+f"(c[0]), "+f"(c[1]), "+f"(c[2]), "+f"(c[3])
        : "r"(a[0]), "r"(a[1]), "r"(a[2]), "r"(a[3]), "r"(b[0]), "r"(b[1]));
}

// ---------------- dtype detector ----------------
__global__ void detect_kernel(const int* __restrict__ ei32) {
    int any = 0;
    for (int i = threadIdx.x; i < 2048; i += 32)
        if (ei32[2 * i + 1] != 0) any = 1;
    any = __any_sync(0xffffffffu, any);
    if (threadIdx.x == 0) g_is64 = any ? 0 : 1;
}

// ---------------- zero kernels ----------------
__global__ void zero_f4(float4* __restrict__ p, int n4) {
    int i = blockIdx.x * blockDim.x + threadIdx.x;
    if (i < n4) p[i] = make_float4(0.f, 0.f, 0.f, 0.f);
}
__global__ void zero_i(int* __restrict__ p, int n) {
    int i = blockIdx.x * blockDim.x + threadIdx.x;
    if (i < n) p[i] = 0;
}

// ---------------- CSR build ----------------
__global__ void hist_kernel(const void* __restrict__ ei, int nE) {
    int e = blockIdx.x * blockDim.x + threadIdx.x;
    if (e >= nE) return;
    atomicAdd(&g_deg[edge_idx(ei, nE + e)], 1);
}

__global__ void scan_sum(int nN) {
    __shared__ int red[1024];
    int t = threadIdx.x;
    int base = blockIdx.x * 4096 + t * 4;
    int s = 0;
#pragma unroll
    for (int q = 0; q < 4; q++)
        if (base + q < nN) s += g_deg[base + q];
    red[t] = s; __syncthreads();
    for (int off = 512; off > 0; off >>= 1) {
        if (t < off) red[t] += red[t + off];
        __syncthreads();
    }
    if (t == 0) g_part[blockIdx.x] = red[0];
}

__global__ void scan_part(int nblk, int nN) {
    if (threadIdx.x == 0) {
        int run = 0;
        for (int i = 0; i < nblk; i++) { g_part2[i] = run; run += g_part[i]; }
        g_off[nN] = run;
    }
}

__global__ void scan_final(int nN) {
    __shared__ int sc[1024];
    int t = threadIdx.x;
    int base = blockIdx.x * 4096 + t * 4;
    int d[4]; int s = 0;
#pragma unroll
    for (int q = 0; q < 4; q++) {
        d[q] = (base + q < nN) ? g_deg[base + q] : 0;
        s += d[q];
    }
    sc[t] = s; __syncthreads();
    for (int off = 1; off < 1024; off <<= 1) {
        int v = (t >= off) ? sc[t - off] : 0;
        __syncthreads();
        sc[t] += v;
        __syncthreads();
    }
    int run = g_part2[blockIdx.x] + sc[t] - s;
#pragma unroll
    for (int q = 0; q < 4; q++) {
        if (base + q < nN) { g_off[base + q] = run; g_cur[base + q] = run; }
        run += d[q];
    }
}

__global__ void fill_kernel(const void* __restrict__ ei, int nE) {
    int e = blockIdx.x * blockDim.x + threadIdx.x;
    if (e >= nE) return;
    int src = edge_idx(ei, e);
    int dst = edge_idx(ei, nE + e);
    int slot = atomicAdd(&g_cur[dst], 1);
    g_esrc[slot] = src;
}

// ---------------- CSR gather: agg[n] = sum_{j in adj(n)} x[src_j] ----------------
__global__ void gather_kernel(const float* __restrict__ x, float* __restrict__ agg, int nN) {
    int wid = threadIdx.x >> 5, lane = threadIdx.x & 31;
    int node = blockIdx.x * 8 + wid;
    if (node >= nN) return;
    int b = g_off[node], e = g_off[node + 1];
    const float4* x4 = (const float4*)x;
    float4 a0 = make_float4(0.f, 0.f, 0.f, 0.f), a1 = a0;
    int j = b;
    for (; j + 1 < e; j += 2) {
        int s0 = g_esrc[j], s1 = g_esrc[j + 1];
        float4 v0 = x4[(size_t)s0 * 32 + lane];
        float4 v1 = x4[(size_t)s1 * 32 + lane];
        a0.x += v0.x; a0.y += v0.y; a0.z += v0.z; a0.w += v0.w;
        a1.x += v1.x; a1.y += v1.y; a1.z += v1.z; a1.w += v1.w;
    }
    if (j < e) {
        int s0 = g_esrc[j];
        float4 v0 = x4[(size_t)s0 * 32 + lane];
        a0.x += v0.x; a0.y += v0.y; a0.z += v0.z; a0.w += v0.w;
    }
    a0.x += a1.x; a0.y += a1.y; a0.z += a1.z; a0.w += a1.w;
    ((float4*)agg)[(size_t)node * 32 + lane] = a0;
}

// ---------------- global pool ----------------
__global__ void pool_kernel(const float* __restrict__ x, const void* __restrict__ batch,
                            float* __restrict__ pool, int n) {
    int gid = blockIdx.x * blockDim.x + threadIdx.x;
    int node = gid >> 5, lane = gid & 31;
    if (node >= n) return;
    int g = edge_idx(batch, node);
    float4 v = ((const float4*)(x + (size_t)node * D))[lane];
    float* p = pool + (size_t)g * D + lane * 4;
    asm volatile("red.global.add.v4.f32 [%0], {%1,%2,%3,%4};"
                 :: "l"(p), "f"(v.x), "f"(v.y), "f"(v.z), "f"(v.w)
                 : "memory");
}

// ---------------- weight prep: split bf16 hi/lo into padded MMA layout ----------------
__global__ void prep_b(const float* __restrict__ W1, const float* __restrict__ W2,
                       const float* __restrict__ hW1, const float* __restrict__ hW2) {
    int m = blockIdx.x;
    const float* src = (m < 3) ? (W1 + m * 16384)
                     : (m < 6) ? (W2 + (m - 3) * 16384)
                     : (m == 6 ? hW1 : hW2);
    uint32_t* dst = g_wtB[m];
    for (int idx = threadIdx.x; idx < 64 * 128; idx += 256) {
        int p = idx >> 7;         // kpair 0..63
        int n = idx & 127;        // col 0..127
        float v0 = src[(2 * p) * 128 + n];
        float v1 = src[(2 * p + 1) * 128 + n];
        __nv_bfloat16 h0 = __float2bfloat16(v0);
        __nv_bfloat16 h1 = __float2bfloat16(v1);
        __nv_bfloat16 l0 = __float2bfloat16(v0 - __bfloat162float(h0));
        __nv_bfloat16 l1 = __float2bfloat16(v1 - __bfloat162float(h1));
        uint32_t hp = (uint32_t)__bfloat16_as_ushort(h0) |
                      ((uint32_t)__bfloat16_as_ushort(h1) << 16);
        uint32_t lp = (uint32_t)__bfloat16_as_ushort(l0) |
                      ((uint32_t)__bfloat16_as_ushort(l1) << 16);
        int nh = n >> 6, c = n & 63;
        dst[(0 * 2 + nh) * 4608 + p * 72 + c] = hp;
        dst[(1 * 2 + nh) * 4608 + p * 72 + c] = lp;
    }
}

__global__ void prep_st(const float* __restrict__ b1, const float* __restrict__ gam,
                        const float* __restrict__ bet, const float* __restrict__ mu,
                        const float* __restrict__ var, const float* __restrict__ b2,
                        const float* __restrict__ hb1, const float* __restrict__ hb2) {
    int m = blockIdx.x, c = threadIdx.x;
    float S = 1.f, T;
    if (m < 3) {
        int i = m * 128 + c;
        S = gam[i] * rsqrtf(var[i] + 1e-5f);
        T = bet[i] + (b1[i] - mu[i]) * S;
    } else if (m < 6) T = b2[(m - 3) * 128 + c];
    else if (m == 6) T = hb1[c];
    else T = hb2[c];
    g_st[m][0][c] = S;
    g_st[m][1][c] = T;
}

// ---------------- HMMA GEMM: C = epi((A[+A2]) @ W + b), tile 128x64 ----------------
// MODE 0: relu   MODE 1: relu (BN already folded into S/T)   MODE 2: none
// smem (u32 units): AH [128][68] @0, AL @8704, BH [64][72] @17408, BL @22016
#define SMEM_U32 26624
template <int MODE>
__global__ void __launch_bounds__(256)
gemm_mma(const float* __restrict__ A, const float* __restrict__ A2,
         const uint32_t* __restrict__ img, const float* __restrict__ stS,
         const float* __restrict__ stT, float* __restrict__ C, int M) {
    extern __shared__ __align__(16) uint32_t sm[];
    uint32_t* AHs = sm;
    uint32_t* ALs = sm + 8704;
    uint32_t* BHs = sm + 17408;
    uint32_t* BLs = sm + 22016;

    int tid = threadIdx.x;
    int row0 = blockIdx.x * 128;
    int nh = blockIdx.y;

    // stage B (pre-swizzled image, linear copy, 4608 u32 per half)
    {
        const uint4* sh = (const uint4*)(img + nh * 4608);
        const uint4* sl = (const uint4*)(img + (2 + nh) * 4608);
        uint4* dh = (uint4*)BHs;
        uint4* dl = (uint4*)BLs;
        for (int i = tid; i < 1152; i += 256) { dh[i] = sh[i]; dl[i] = sl[i]; }
    }

    // stage A: thread handles row tid>>1, col half tid&1 (64 floats)
    {
        int r = tid >> 1, half = tid & 1;
        int gr = row0 + r;
        bool v = gr < M;
        const float4* Ar  = (const float4*)(A + (size_t)(v ? gr : 0) * D) + half * 16;
        const float4* A2r = A2 ? (const float4*)(A2 + (size_t)(v ? gr : 0) * D) + half * 16 : nullptr;
#pragma unroll 4
        for (int j = 0; j < 16; j++) {
            float4 a = v ? Ar[j] : make_float4(0.f, 0.f, 0.f, 0.f);
            if (A2r && v) {
                float4 b = A2r[j];
                a.x += b.x; a.y += b.y; a.z += b.z; a.w += b.w;
            }
            float f[4] = {a.x, a.y, a.z, a.w};
            uint32_t hp[2], lp[2];
#pragma unroll
            for (int q = 0; q < 2; q++) {
                __nv_bfloat16 h0 = __float2bfloat16(f[2 * q]);
                __nv_bfloat16 h1 = __float2bfloat16(f[2 * q + 1]);
                __nv_bfloat16 l0 = __float2bfloat16(f[2 * q]     - __bfloat162float(h0));
                __nv_bfloat16 l1 = __float2bfloat16(f[2 * q + 1] - __bfloat162float(h1));
                hp[q] = (uint32_t)__bfloat16_as_ushort(h0) |
                        ((uint32_t)__bfloat16_as_ushort(h1) << 16);
                lp[q] = (uint32_t)__bfloat16_as_ushort(l0) |
                        ((uint32_t)__bfloat16_as_ushort(l1) << 16);
            }
            int p = half * 32 + j * 2;       // kpair index (even)
            *(uint2*)&AHs[r * 68 + p] = make_uint2(hp[0], hp[1]);
            *(uint2*)&ALs[r * 68 + p] = make_uint2(lp[0], lp[1]);
        }
    }
    __syncthreads();

    int lane = tid & 31, wid = tid >> 5;
    int g = lane >> 2, tg = lane & 3;
    int moff = (wid & 3) * 32, noff = (wid >> 2) * 32;

    float Cr[2][4][4];
#pragma unroll
    for (int i = 0; i < 2; i++)
#pragma unroll
        for (int j = 0; j < 4; j++)
#pragma unroll
            for (int q = 0; q < 4; q++) Cr[i][j][q] = 0.f;

#pragma unroll
    for (int ks = 0; ks < 8; ks++) {
        int kp = ks * 8;
        uint32_t ah[2][4], al[2][4], bh[4][2], bl[4][2];
#pragma unroll
        for (int mf = 0; mf < 2; mf++) {
            int r = moff + mf * 16 + g;
            ah[mf][0] = AHs[r * 68 + kp + tg];
            ah[mf][1] = AHs[(r + 8) * 68 + kp + tg];
            ah[mf][2] = AHs[r * 68 + kp + tg + 4];
            ah[mf][3] = AHs[(r + 8) * 68 + kp + tg + 4];
            al[mf][0] = ALs[r * 68 + kp + tg];
            al[mf][1] = ALs[(r + 8) * 68 + kp + tg];
            al[mf][2] = ALs[r * 68 + kp + tg + 4];
            al[mf][3] = ALs[(r + 8) * 68 + kp + tg + 4];
        }
#pragma unroll
        for (int nf = 0; nf < 4; nf++) {
            int cn = noff + nf * 8 + g;
            bh[nf][0] = BHs[(kp + tg) * 72 + cn];
            bh[nf][1] = BHs[(kp + tg + 4) * 72 + cn];
            bl[nf][0] = BLs[(kp + tg) * 72 + cn];
            bl[nf][1] = BLs[(kp + tg + 4) * 72 + cn];
        }
#pragma unroll
        for (int mf = 0; mf < 2; mf++)
#pragma unroll
            for (int nf = 0; nf < 4; nf++) {
                mma16816(Cr[mf][nf], ah[mf], bh[nf]);
                mma16816(Cr[mf][nf], al[mf], bh[nf]);
                mma16816(Cr[mf][nf], ah[mf], bl[nf]);
            }
    }

    // epilogue
    int colb = nh * 64 + noff;
#pragma unroll
    for (int mf = 0; mf < 2; mf++)
#pragma unroll
        for (int nf = 0; nf < 4; nf++) {
            int col = colb + nf * 8 + 2 * tg;
            float s0 = __ldg(stS + col), s1 = __ldg(stS + col + 1);
            float t0 = __ldg(stT + col), t1 = __ldg(stT + col + 1);
#pragma unroll
            for (int hh = 0; hh < 2; hh++) {
                int row = row0 + moff + mf * 16 + g + hh * 8;
                if (row < M) {
                    float v0 = Cr[mf][nf][hh * 2 + 0] * s0 + t0;
                    float v1 = Cr[mf][nf][hh * 2 + 1] * s1 + t1;
                    if (MODE != 2) { v0 = fmaxf(v0, 0.f); v1 = fmaxf(v1, 0.f); }
                    *(float2*)(C + (size_t)row * D + col) = make_float2(v0, v1);
                }
            }
        }
}

extern "C" void kernel_launch(void* const* d_in, const int* in_sizes, int n_in,
                              void* d_out, int out_size) {
    const float* x    = (const float*)d_in[0];
    const void* ei    = d_in[1];
    const void* batch = d_in[2];
    const float* W1   = (const float*)d_in[3];
    const float* b1   = (const float*)d_in[4];
    const float* gam  = (const float*)d_in[5];
    const float* bet  = (const float*)d_in[6];
    const float* mu   = (const float*)d_in[7];
    const float* var  = (const float*)d_in[8];
    const float* W2   = (const float*)d_in[9];
    const float* b2   = (const float*)d_in[10];
    const float* hW1  = (const float*)d_in[11];
    const float* hb1  = (const float*)d_in[12];
    const float* hW2  = (const float*)d_in[13];
    const float* hb2  = (const float*)d_in[14];
    float* out = (float*)d_out;

    int nN = in_sizes[0] / D;          // 100000
    int nE = in_sizes[1] / 2;          // 1600000
    int nG = out_size / D;             // 1024

    void* p;
    cudaGetSymbolAddress(&p, g_agg);  float* agg  = (float*)p;
    cudaGetSymbolAddress(&p, g_h);    float* h    = (float*)p;
    cudaGetSymbolAddress(&p, g_x1);   float* x1   = (float*)p;
    cudaGetSymbolAddress(&p, g_x2);   float* x2   = (float*)p;
    cudaGetSymbolAddress(&p, g_pool); float* pool = (float*)p;
    cudaGetSymbolAddress(&p, g_wtB);  uint32_t* wt = (uint32_t*)p;
    cudaGetSymbolAddress(&p, g_st);   float* st = (float*)p;
    cudaGetSymbolAddress(&p, g_deg);  int* deg = (int*)p;

    static bool attr_done = false;
    if (!attr_done) {
        cudaFuncSetAttribute(gemm_mma<0>, cudaFuncAttributeMaxDynamicSharedMemorySize, SMEM_U32 * 4);
        cudaFuncSetAttribute(gemm_mma<1>, cudaFuncAttributeMaxDynamicSharedMemorySize, SMEM_U32 * 4);
        cudaFuncSetAttribute(gemm_mma<2>, cudaFuncAttributeMaxDynamicSharedMemorySize, SMEM_U32 * 4);
        attr_done = true;
    }

    int edgeBlocks = (nE + 255) / 256;
    int scanBlocks = (nN + 4095) / 4096;
    dim3 ggrid((nN + 127) / 128, 2);
    dim3 hgrid((nG + 127) / 128, 2);

    detect_kernel<<<1, 32>>>((const int*)ei);
    prep_b<<<8, 256>>>(W1, W2, hW1, hW2);
    prep_st<<<8, 128>>>(b1, gam, bet, mu, var, b2, hb1, hb2);

    // CSR build
    zero_i<<<(nN + 1023) / 1024, 1024>>>(deg, nN);
    hist_kernel<<<edgeBlocks, 256>>>(ei, nE);
    scan_sum<<<scanBlocks, 1024>>>(nN);
    scan_part<<<1, 32>>>(scanBlocks, nN);
    scan_final<<<scanBlocks, 1024>>>(nN);
    fill_kernel<<<edgeBlocks, 256>>>(ei, nE);

    const float* xin = x;
    float* xbuf[2] = {x1, x2};
    for (int l = 0; l < 3; l++) {
        gather_kernel<<<(nN + 7) / 8, 256>>>(xin, agg, nN);
        gemm_mma<1><<<ggrid, 256, SMEM_U32 * 4>>>(xin, agg, wt + (size_t)l * 4 * 4608,
                                                  st + l * 256, st + l * 256 + 128, h, nN);
        float* xo = xbuf[l & 1];
        gemm_mma<0><<<ggrid, 256, SMEM_U32 * 4>>>(h, nullptr, wt + (size_t)(3 + l) * 4 * 4608,
                                                  st + (3 + l) * 256, st + (3 + l) * 256 + 128,
                                                  xo, nN);
        xin = xo;
    }

    zero_f4<<<(nG * 32 + 255) / 256, 256>>>((float4*)pool, nG * 32);
    pool_kernel<<<(nN * 32 + 255) / 256, 256>>>(xin, batch, pool, nN);

    gemm_mma<0><<<hgrid, 256, SMEM_U32 * 4>>>(pool, nullptr, wt + (size_t)6 * 4 * 4608,
                                              st + 6 * 256, st + 6 * 256 + 128, h, nG);
    gemm_mma<2><<<hgrid, 256, SMEM_U32 * 4>>>(h, nullptr, wt + (size_t)7 * 4 * 4608,
                                              st + 7 * 256, st + 7 * 256 + 128, out, nG);
}

// round 6
// speedup vs baseline: 1.9233x; 1.2593x over previous
#include <cuda_runtime.h>
#include <cuda_bf16.h>
#include <cstdint>

#define NN_MAX 100000
#define NG_MAX 1024
#define D 128
#define NE_MAX 1600000

// ---------------- device scratch (allocation-free rule) ----------------
__device__ float4 g_agg [NN_MAX * D / 4];
__device__ float4 g_h   [NN_MAX * D / 4];
__device__ float4 g_x1  [NN_MAX * D / 4];
__device__ float4 g_x2  [NN_MAX * D / 4];
__device__ float4 g_pool[NG_MAX * D / 4];
// CSR
__device__ int g_deg [NN_MAX + 64];
__device__ int g_off [NN_MAX + 64];
__device__ int g_cur [NN_MAX + 64];
__device__ int g_esrc[NE_MAX];
__device__ int g_part [64];
__device__ int g_part2[64];
// weight images, fragment-major: per matrix 16384 u32 = [hi 8192][lo 8192]
// hi idx = ((nb*8 + ks)*32 + lane)*2 + kh   (nb=col>>3, lane=(col&7)*4+tg)
__device__ uint32_t g_wtB[8][16384];
__device__ float g_st[8][2][128];     // [matrix][S/T][col]
__device__ int g_is64;

// ---------------- helpers ----------------
__device__ __forceinline__ int edge_idx(const void* ei, int i) {
    if (g_is64) return (int)((const long long*)ei)[i];
    return ((const int*)ei)[i];
}

__device__ __forceinline__ void mma16816(float* c, const uint32_t* a, const uint32_t* b) {
    asm volatile(
        "mma.sync.aligned.m16n8k16.row.col.f32.bf16.bf16.f32 "
        "{%0,%1,%2,%3}, {%4,%5,%6,%7}, {%8,%9}, {%0,%1,%2,%3};"
        : "+f"(c[0]), "+f"(c[1]), "+f"(c[2]), "+f"(c[3])
        : "r"(a[0]), "r"(a[1]), "r"(a[2]), "r"(a[3]), "r"(b[0]), "r"(b[1]));
}

__device__ __forceinline__ void ldm_x4(uint32_t& a0, uint32_t& a1, uint32_t& a2,
                                       uint32_t& a3, uint32_t addr) {
    asm volatile("ldmatrix.sync.aligned.m8n8.x4.shared.b16 {%0,%1,%2,%3}, [%4];"
                 : "=r"(a0), "=r"(a1), "=r"(a2), "=r"(a3) : "r"(addr));
}

__device__ __forceinline__ uint32_t smem_u32(const void* p) {
    uint32_t a;
    asm("{ .reg .u64 t; cvta.to.shared.u64 t, %1; cvt.u32.u64 %0, t; }"
        : "=r"(a) : "l"(p));
    return a;
}

__device__ __forceinline__ uint32_t pack_bf16_hi(float a, float b, uint32_t& lo) {
    __nv_bfloat16 h0 = __float2bfloat16(a);
    __nv_bfloat16 h1 = __float2bfloat16(b);
    __nv_bfloat16 l0 = __float2bfloat16(a - __bfloat162float(h0));
    __nv_bfloat16 l1 = __float2bfloat16(b - __bfloat162float(h1));
    lo = (uint32_t)__bfloat16_as_ushort(l0) | ((uint32_t)__bfloat16_as_ushort(l1) << 16);
    return (uint32_t)__bfloat16_as_ushort(h0) | ((uint32_t)__bfloat16_as_ushort(h1) << 16);
}

// ---------------- dtype detector ----------------
__global__ void detect_kernel(const int* __restrict__ ei32) {
    int any = 0;
    for (int i = threadIdx.x; i < 2048; i += 32)
        if (ei32[2 * i + 1] != 0) any = 1;
    any = __any_sync(0xffffffffu, any);
    if (threadIdx.x == 0) g_is64 = any ? 0 : 1;
}

// ---------------- zero kernels ----------------
__global__ void zero_f4(float4* __restrict__ p, int n4) {
    int i = blockIdx.x * blockDim.x + threadIdx.x;
    if (i < n4) p[i] = make_float4(0.f, 0.f, 0.f, 0.f);
}
__global__ void zero_i(int* __restrict__ p, int n) {
    int i = blockIdx.x * blockDim.x + threadIdx.x;
    if (i < n) p[i] = 0;
}

// ---------------- CSR build ----------------
__global__ void hist_kernel(const void* __restrict__ ei, int nE) {
    int e = blockIdx.x * blockDim.x + threadIdx.x;
    if (e >= nE) return;
    atomicAdd(&g_deg[edge_idx(ei, nE + e)], 1);
}

__global__ void scan_sum(int nN) {
    __shared__ int red[1024];
    int t = threadIdx.x;
    int base = blockIdx.x * 4096 + t * 4;
    int s = 0;
#pragma unroll
    for (int q = 0; q < 4; q++)
        if (base + q < nN) s += g_deg[base + q];
    red[t] = s; __syncthreads();
    for (int off = 512; off > 0; off >>= 1) {
        if (t < off) red[t] += red[t + off];
        __syncthreads();
    }
    if (t == 0) g_part[blockIdx.x] = red[0];
}

__global__ void scan_part(int nblk, int nN) {
    if (threadIdx.x == 0) {
        int run = 0;
        for (int i = 0; i < nblk; i++) { g_part2[i] = run; run += g_part[i]; }
        g_off[nN] = run;
    }
}

__global__ void scan_final(int nN) {
    __shared__ int sc[1024];
    int t = threadIdx.x;
    int base = blockIdx.x * 4096 + t * 4;
    int d[4]; int s = 0;
#pragma unroll
    for (int q = 0; q < 4; q++) {
        d[q] = (base + q < nN) ? g_deg[base + q] : 0;
        s += d[q];
    }
    sc[t] = s; __syncthreads();
    for (int off = 1; off < 1024; off <<= 1) {
        int v = (t >= off) ? sc[t - off] : 0;
        __syncthreads();
        sc[t] += v;
        __syncthreads();
    }
    int run = g_part2[blockIdx.x] + sc[t] - s;
#pragma unroll
    for (int q = 0; q < 4; q++) {
        if (base + q < nN) { g_off[base + q] = run; g_cur[base + q] = run; }
        run += d[q];
    }
}

__global__ void fill_kernel(const void* __restrict__ ei, int nE) {
    int e = blockIdx.x * blockDim.x + threadIdx.x;
    if (e >= nE) return;
    int src = edge_idx(ei, e);
    int dst = edge_idx(ei, nE + e);
    int slot = atomicAdd(&g_cur[dst], 1);
    g_esrc[slot] = src;
}

// ---------------- CSR gather ----------------
__global__ void gather_kernel(const float* __restrict__ x, float* __restrict__ agg, int nN) {
    int wid = threadIdx.x >> 5, lane = threadIdx.x & 31;
    int node = blockIdx.x * 8 + wid;
    if (node >= nN) return;
    int b = g_off[node], e = g_off[node + 1];
    const float4* x4 = (const float4*)x;
    float4 a0 = make_float4(0.f, 0.f, 0.f, 0.f), a1 = a0, a2 = a0, a3 = a0;
    int j = b;
    for (; j + 3 < e; j += 4) {
        int s0 = g_esrc[j], s1 = g_esrc[j + 1], s2 = g_esrc[j + 2], s3 = g_esrc[j + 3];
        float4 v0 = x4[(size_t)s0 * 32 + lane];
        float4 v1 = x4[(size_t)s1 * 32 + lane];
        float4 v2 = x4[(size_t)s2 * 32 + lane];
        float4 v3 = x4[(size_t)s3 * 32 + lane];
        a0.x += v0.x; a0.y += v0.y; a0.z += v0.z; a0.w += v0.w;
        a1.x += v1.x; a1.y += v1.y; a1.z += v1.z; a1.w += v1.w;
        a2.x += v2.x; a2.y += v2.y; a2.z += v2.z; a2.w += v2.w;
        a3.x += v3.x; a3.y += v3.y; a3.z += v3.z; a3.w += v3.w;
    }
    for (; j < e; j++) {
        float4 v0 = x4[(size_t)g_esrc[j] * 32 + lane];
        a0.x += v0.x; a0.y += v0.y; a0.z += v0.z; a0.w += v0.w;
    }
    a0.x += a1.x + a2.x + a3.x;
    a0.y += a1.y + a2.y + a3.y;
    a0.z += a1.z + a2.z + a3.z;
    a0.w += a1.w + a2.w + a3.w;
    ((float4*)agg)[(size_t)node * 32 + lane] = a0;
}

// ---------------- global pool ----------------
__global__ void pool_kernel(const float* __restrict__ x, const void* __restrict__ batch,
                            float* __restrict__ pool, int n) {
    int gid = blockIdx.x * blockDim.x + threadIdx.x;
    int node = gid >> 5, lane = gid & 31;
    if (node >= n) return;
    int g = edge_idx(batch, node);
    float4 v = ((const float4*)(x + (size_t)node * D))[lane];
    float* p = pool + (size_t)g * D + lane * 4;
    asm volatile("red.global.add.v4.f32 [%0], {%1,%2,%3,%4};"
                 :: "l"(p), "f"(v.x), "f"(v.y), "f"(v.z), "f"(v.w)
                 : "memory");
}

// ---------------- weight prep: fragment-major split-bf16 B image ----------------
__global__ void prep_b(const float* __restrict__ W1, const float* __restrict__ W2,
                       const float* __restrict__ hW1, const float* __restrict__ hW2) {
    int m = blockIdx.x;
    const float* src = (m < 3) ? (W1 + m * 16384)
                     : (m < 6) ? (W2 + (m - 3) * 16384)
                     : (m == 6 ? hW1 : hW2);
    uint32_t* dst = g_wtB[m];
    for (int idx = threadIdx.x; idx < 64 * 128; idx += 256) {
        int p = idx >> 7;         // kpair 0..63
        int n = idx & 127;        // col 0..127
        uint32_t lo;
        uint32_t hi = pack_bf16_hi(src[(2 * p) * 128 + n], src[(2 * p + 1) * 128 + n], lo);
        int nb = n >> 3, gB = n & 7;
        int ks = p >> 3, q = p & 7, tg = q & 3, kh = q >> 2;
        int lane = gB * 4 + tg;
        int fi = ((nb * 8 + ks) * 32 + lane) * 2 + kh;
        dst[fi] = hi;
        dst[8192 + fi] = lo;
    }
}

__global__ void prep_st(const float* __restrict__ b1, const float* __restrict__ gam,
                        const float* __restrict__ bet, const float* __restrict__ mu,
                        const float* __restrict__ var, const float* __restrict__ b2,
                        const float* __restrict__ hb1, const float* __restrict__ hb2) {
    int m = blockIdx.x, c = threadIdx.x;
    float S = 1.f, T;
    if (m < 3) {
        int i = m * 128 + c;
        S = gam[i] * rsqrtf(var[i] + 1e-5f);
        T = bet[i] + (b1[i] - mu[i]) * S;
    } else if (m < 6) T = b2[(m - 3) * 128 + c];
    else if (m == 6) T = hb1[c];
    else T = hb2[c];
    g_st[m][0][c] = S;
    g_st[m][1][c] = T;
}

// ---------------- HMMA GEMM: C = epi((A[+A2]) @ W + b), tile 128x128 -----------
// 512 threads = 16 warps, warp tile 32x32. A row-major stride 68 u32 (ldmatrix),
// B fragment-major (pre-built). 3-term bf16 split.
// smem u32 offsets: AH 0, AL 8704, BH 17408, BL 25600; total 33792 u32 (132KB)
#define AH_OFF 0
#define AL_OFF 8704
#define BH_OFF 17408
#define BL_OFF 25600
#define SMEM_BYTES (33792 * 4)

template <int MODE>  // 0: relu, 2: none (BN folded into S/T for layer1)
__global__ void __launch_bounds__(512)
gemm_mma(const float* __restrict__ A, const float* __restrict__ A2,
         const uint32_t* __restrict__ img, const float* __restrict__ stS,
         const float* __restrict__ stT, float* __restrict__ C, int M) {
    extern __shared__ __align__(16) uint32_t sm[];
    int tid = threadIdx.x;
    int row0 = blockIdx.x * 128;

    // stage B: linear copy of 16384 u32 (already fragment-major)
    {
        const uint4* s4 = (const uint4*)img;
        uint4* dh = (uint4*)(sm + BH_OFF);
#pragma unroll
        for (int i = 0; i < 8; i++) dh[tid + i * 512] = s4[tid + i * 512];
    }

    // stage A: thread -> row tid>>2, quarter tid&3 (32 floats = 16 kpairs)
    {
        int r = tid >> 2, cq = tid & 3;
        int gr = row0 + r;
        bool v = gr < M;
        const float4* Ar  = (const float4*)(A + (size_t)(v ? gr : 0) * D) + cq * 8;
        const float4* A2r = A2 ? (const float4*)(A2 + (size_t)(v ? gr : 0) * D) + cq * 8 : nullptr;
        uint32_t hp[16], lp[16];
#pragma unroll
        for (int j = 0; j < 8; j++) {
            float4 a = v ? Ar[j] : make_float4(0.f, 0.f, 0.f, 0.f);
            if (A2r && v) {
                float4 b = A2r[j];
                a.x += b.x; a.y += b.y; a.z += b.z; a.w += b.w;
            }
            hp[2 * j]     = pack_bf16_hi(a.x, a.y, lp[2 * j]);
            hp[2 * j + 1] = pack_bf16_hi(a.z, a.w, lp[2 * j + 1]);
        }
        uint4* dH = (uint4*)(sm + AH_OFF + r * 68 + cq * 16);
        uint4* dL = (uint4*)(sm + AL_OFF + r * 68 + cq * 16);
#pragma unroll
        for (int t = 0; t < 4; t++) {
            dH[t] = make_uint4(hp[4 * t], hp[4 * t + 1], hp[4 * t + 2], hp[4 * t + 3]);
            dL[t] = make_uint4(lp[4 * t], lp[4 * t + 1], lp[4 * t + 2], lp[4 * t + 3]);
        }
    }
    __syncthreads();

    int lane = tid & 31, wid = tid >> 5;
    int g = lane >> 2, tg = lane & 3;
    int mq = wid & 3, nq = wid >> 2;           // moff = mq*32, noff = nq*32

    uint32_t sbase = smem_u32(sm);
    // ldmatrix address bases for the two 16-row m-fragments (hi and lo buffers)
    uint32_t aRow = (uint32_t)(mq * 32 + (lane & 15));
    uint32_t aCol = (uint32_t)((lane >> 4) * 4);
    uint32_t adrH0 = sbase + (AH_OFF + aRow * 68 + aCol) * 4;
    uint32_t adrH1 = adrH0 + 16 * 68 * 4;
    uint32_t adrL0 = adrH0 + (AL_OFF - AH_OFF) * 4;
    uint32_t adrL1 = adrL0 + 16 * 68 * 4;

    const uint2* BH2 = (const uint2*)(sm + BH_OFF);
    const uint2* BL2 = (const uint2*)(sm + BL_OFF);

    float Cr[2][4][4];
#pragma unroll
    for (int i = 0; i < 2; i++)
#pragma unroll
        for (int j = 0; j < 4; j++)
#pragma unroll
            for (int q = 0; q < 4; q++) Cr[i][j][q] = 0.f;

#pragma unroll 2
    for (int ks = 0; ks < 8; ks++) {
        uint32_t cb = ks * 32;   // 8 kpairs = 32 bytes
        uint32_t ah[2][4], al[2][4], bh[4][2], bl[4][2];
        ldm_x4(ah[0][0], ah[0][1], ah[0][2], ah[0][3], adrH0 + cb);
        ldm_x4(ah[1][0], ah[1][1], ah[1][2], ah[1][3], adrH1 + cb);
        ldm_x4(al[0][0], al[0][1], al[0][2], al[0][3], adrL0 + cb);
        ldm_x4(al[1][0], al[1][1], al[1][2], al[1][3], adrL1 + cb);
#pragma unroll
        for (int nf = 0; nf < 4; nf++) {
            int fi = ((nq * 4 + nf) * 8 + ks) * 32 + lane;
            uint2 h2 = BH2[fi];
            uint2 l2 = BL2[fi];
            bh[nf][0] = h2.x; bh[nf][1] = h2.y;
            bl[nf][0] = l2.x; bl[nf][1] = l2.y;
        }
#pragma unroll
        for (int mf = 0; mf < 2; mf++)
#pragma unroll
            for (int nf = 0; nf < 4; nf++) {
                mma16816(Cr[mf][nf], ah[mf], bh[nf]);
                mma16816(Cr[mf][nf], al[mf], bh[nf]);
                mma16816(Cr[mf][nf], ah[mf], bl[nf]);
            }
    }

    // epilogue
#pragma unroll
    for (int mf = 0; mf < 2; mf++)
#pragma unroll
        for (int nf = 0; nf < 4; nf++) {
            int col = nq * 32 + nf * 8 + 2 * tg;
            float s0 = __ldg(stS + col), s1 = __ldg(stS + col + 1);
            float t0 = __ldg(stT + col), t1 = __ldg(stT + col + 1);
#pragma unroll
            for (int hh = 0; hh < 2; hh++) {
                int row = row0 + mq * 32 + mf * 16 + g + hh * 8;
                if (row < M) {
                    float v0 = Cr[mf][nf][hh * 2 + 0] * s0 + t0;
                    float v1 = Cr[mf][nf][hh * 2 + 1] * s1 + t1;
                    if (MODE != 2) { v0 = fmaxf(v0, 0.f); v1 = fmaxf(v1, 0.f); }
                    *(float2*)(C + (size_t)row * D + col) = make_float2(v0, v1);
                }
            }
        }
}

extern "C" void kernel_launch(void* const* d_in, const int* in_sizes, int n_in,
                              void* d_out, int out_size) {
    const float* x    = (const float*)d_in[0];
    const void* ei    = d_in[1];
    const void* batch = d_in[2];
    const float* W1   = (const float*)d_in[3];
    const float* b1   = (const float*)d_in[4];
    const float* gam  = (const float*)d_in[5];
    const float* bet  = (const float*)d_in[6];
    const float* mu   = (const float*)d_in[7];
    const float* var  = (const float*)d_in[8];
    const float* W2   = (const float*)d_in[9];
    const float* b2   = (const float*)d_in[10];
    const float* hW1  = (const float*)d_in[11];
    const float* hb1  = (const float*)d_in[12];
    const float* hW2  = (const float*)d_in[13];
    const float* hb2  = (const float*)d_in[14];
    float* out = (float*)d_out;

    int nN = in_sizes[0] / D;          // 100000
    int nE = in_sizes[1] / 2;          // 1600000
    int nG = out_size / D;             // 1024

    void* p;
    cudaGetSymbolAddress(&p, g_agg);  float* agg  = (float*)p;
    cudaGetSymbolAddress(&p, g_h);    float* h    = (float*)p;
    cudaGetSymbolAddress(&p, g_x1);   float* x1   = (float*)p;
    cudaGetSymbolAddress(&p, g_x2);   float* x2   = (float*)p;
    cudaGetSymbolAddress(&p, g_pool); float* pool = (float*)p;
    cudaGetSymbolAddress(&p, g_wtB);  uint32_t* wt = (uint32_t*)p;
    cudaGetSymbolAddress(&p, g_st);   float* st = (float*)p;
    cudaGetSymbolAddress(&p, g_deg);  int* deg = (int*)p;

    cudaFuncSetAttribute(gemm_mma<0>, cudaFuncAttributeMaxDynamicSharedMemorySize, SMEM_BYTES);
    cudaFuncSetAttribute(gemm_mma<1>, cudaFuncAttributeMaxDynamicSharedMemorySize, SMEM_BYTES);
    cudaFuncSetAttribute(gemm_mma<2>, cudaFuncAttributeMaxDynamicSharedMemorySize, SMEM_BYTES);

    int edgeBlocks = (nE + 255) / 256;
    int scanBlocks = (nN + 4095) / 4096;
    int ggrid = (nN + 127) / 128;
    int hgrid = (nG + 127) / 128;

    detect_kernel<<<1, 32>>>((const int*)ei);
    prep_b<<<8, 256>>>(W1, W2, hW1, hW2);
    prep_st<<<8, 128>>>(b1, gam, bet, mu, var, b2, hb1, hb2);

    // CSR build
    zero_i<<<(nN + 1023) / 1024, 1024>>>(deg, nN);
    hist_kernel<<<edgeBlocks, 256>>>(ei, nE);
    scan_sum<<<scanBlocks, 1024>>>(nN);
    scan_part<<<1, 32>>>(scanBlocks, nN);
    scan_final<<<scanBlocks, 1024>>>(nN);
    fill_kernel<<<edgeBlocks, 256>>>(ei, nE);

    const float* xin = x;
    float* xbuf[2] = {x1, x2};
    for (int l = 0; l < 3; l++) {
        gather_kernel<<<(nN + 7) / 8, 256>>>(xin, agg, nN);
        gemm_mma<1><<<ggrid, 512, SMEM_BYTES>>>(xin, agg, wt + (size_t)l * 16384,
                                                st + l * 256, st + l * 256 + 128, h, nN);
        float* xo = xbuf[l & 1];
        gemm_mma<0><<<ggrid, 512, SMEM_BYTES>>>(h, nullptr, wt + (size_t)(3 + l) * 16384,
                                                st + (3 + l) * 256, st + (3 + l) * 256 + 128,
                                                xo, nN);
        xin = xo;
    }

    zero_f4<<<(nG * 32 + 255) / 256, 256>>>((float4*)pool, nG * 32);
    pool_kernel<<<(nN * 32 + 255) / 256, 256>>>(xin, batch, pool, nN);

    gemm_mma<0><<<hgrid, 512, SMEM_BYTES>>>(pool, nullptr, wt + (size_t)6 * 16384,
                                            st + 6 * 256, st + 6 * 256 + 128, h, nG);
    gemm_mma<2><<<hgrid, 512, SMEM_BYTES>>>(h, nullptr, wt + (size_t)7 * 16384,
                                            st + 7 * 256, st + 7 * 256 + 128, out, nG);
}